// round 6
// baseline (speedup 1.0000x reference)
#include <cuda_runtime.h>
#include <math.h>

#define TT 10
#define CH 16
#define HH 16
#define WW 264
#define HW (HH*WW)            // 4224
#define DD (CH*HH*WW)         // 67584
#define D4 (DD/4)             // 16896
#define NPAIR 45              // valid (b,t) warp pairs, t in [1,b]

// Scratch (static device globals; no allocation allowed)
__device__ float g_warp[NPAIR * DD];      // 45 warped rows, compact
__device__ float g_dots[TT * 10 * 10];    // per-b row-space Gram (i<=j filled)

__device__ __forceinline__ int tri(int b) { return b * (b - 1) / 2; }

// ---------------------------------------------------------------------------
// Kernel 1: bilinear warp of the 45 valid (b,t) pairs.
// grid: (HW/128 = 33, NPAIR), block 128. One thread = one spatial pixel.
// Pose computed uniformly by every thread (broadcast loads, no barrier).
// Channel loop batched 8-wide: 32 independent gathers in flight per thread.
// Block (0,0) zeroes g_dots for the score kernel's atomics.
// ---------------------------------------------------------------------------
__global__ __launch_bounds__(128) void warp_kernel(const float* __restrict__ ff,
                                                   const float* __restrict__ dp) {
    int p = blockIdx.y;
    int tid = threadIdx.x;

    if (blockIdx.x == 0 && p == 0) {
        for (int i = tid; i < TT * 100; i += 128) g_dots[i] = 0.f;
    }

    // derive (b, t) and pose = P[t-1] - P[b]; uniform across the block
    int b = 1;
    while (tri(b) + b <= p) b++;
    int t = p - tri(b) + 1;                 // source frame, 1..b
    float ax = 0.f, ay = 0.f, az = 0.f;     // P[t-1]
    float bx = 0.f, by = 0.f, bz = 0.f;     // P[b]
    for (int j = 0; j < b; j++) {
        float d0 = __ldg(dp + 3 * j);
        float d1 = __ldg(dp + 3 * j + 1);
        float d2 = __ldg(dp + 3 * j + 2);
        bx += d0; by += d1; bz += d2;
        if (j < t - 1) { ax += d0; ay += d1; az += d2; }
    }
    float yaw = az - bz;
    float cs = cosf(yaw), sn = sinf(yaw);
    float dx = ax - bx,   dy = ay - by;

    int pix = blockIdx.x * 128 + tid;       // 0..HW-1
    int x = pix % WW;
    int y = pix / WW;

    float xs = (2.f * (float)x + 1.f) / (float)WW - 1.f;
    float ys = (2.f * (float)y + 1.f) / (float)HH - 1.f;
    float gx = cs * xs + sn * ys + dx;
    float gy = -sn * xs + cs * ys + dy;
    float ix = ((gx + 1.f) * (float)WW - 1.f) * 0.5f;
    float iy = ((gy + 1.f) * (float)HH - 1.f) * 0.5f;

    float ix0f = floorf(ix), iy0f = floorf(iy);
    float wx1 = ix - ix0f, wx0 = 1.f - wx1;
    float wy1 = iy - iy0f, wy0 = 1.f - wy1;

    int ix0 = (int)ix0f, iy0 = (int)iy0f;
    int ix1 = ix0 + 1,   iy1 = iy0 + 1;
    float vx0 = (ix0 >= 0 && ix0 < WW) ? 1.f : 0.f;
    float vx1 = (ix1 >= 0 && ix1 < WW) ? 1.f : 0.f;
    float vy0 = (iy0 >= 0 && iy0 < HH) ? 1.f : 0.f;
    float vy1 = (iy1 >= 0 && iy1 < HH) ? 1.f : 0.f;
    int cx0 = min(max(ix0, 0), WW - 1);
    int cx1 = min(max(ix1, 0), WW - 1);
    int cy0 = min(max(iy0, 0), HH - 1);
    int cy1 = min(max(iy1, 0), HH - 1);

    float w00 = wx0 * wy0 * vx0 * vy0;
    float w01 = wx1 * wy0 * vx1 * vy0;
    float w10 = wx0 * wy1 * vx0 * vy1;
    float w11 = wx1 * wy1 * vx1 * vy1;
    int o00 = cy0 * WW + cx0;
    int o01 = cy0 * WW + cx1;
    int o10 = cy1 * WW + cx0;
    int o11 = cy1 * WW + cx1;

    const float* src = ff + t * DD;
    float* dst = g_warp + p * DD + pix;
    #pragma unroll
    for (int cb = 0; cb < CH; cb += 8) {
        float a00[8], a01[8], a10[8], a11[8];
        #pragma unroll
        for (int c = 0; c < 8; c++) {
            const float* s = src + (cb + c) * HW;
            a00[c] = __ldg(s + o00);
            a01[c] = __ldg(s + o01);
            a10[c] = __ldg(s + o10);
            a11[c] = __ldg(s + o11);
        }
        #pragma unroll
        for (int c = 0; c < 8; c++) {
            dst[(cb + c) * HW] =
                w00 * a00[c] + w01 * a01[c] + w10 * a10[c] + w11 * a11[c];
        }
    }
}

// ---------------------------------------------------------------------------
// Kernel 2: full per-b Gram. grid: (33, TT), block 128.
// Each block walks a chunk of all (b+1) rows and accumulates ALL
// (b+1)(b+2)/2 pairwise dots in registers; each row read once per b.
// Exactly 4 float4 iterations per thread (D4 = 33*128*4).
// ---------------------------------------------------------------------------
__global__ __launch_bounds__(128) void score_kernel(const float* __restrict__ ff) {
    int b = blockIdx.y;
    int nr = b + 1;

    const float4* rows[10];
    #pragma unroll
    for (int j = 0; j < 10; j++) {
        if (j < nr) {
            const float* rp = (j == b) ? (ff + b * DD)
                                       : (g_warp + (tri(b) + j) * DD);
            rows[j] = (const float4*)rp;
        }
    }

    float acc[55];
    #pragma unroll
    for (int k = 0; k < 55; k++) acc[k] = 0.f;

    for (int d = blockIdx.x * 128 + threadIdx.x; d < D4; d += 33 * 128) {
        float4 v[10];
        #pragma unroll
        for (int j = 0; j < 10; j++)
            if (j < nr) v[j] = rows[j][d];
        #pragma unroll
        for (int i = 0; i < 10; i++) {
            if (i < nr) {
                #pragma unroll
                for (int j = 0; j <= i; j++) {
                    acc[i * (i + 1) / 2 + j] +=
                        v[i].x * v[j].x + v[i].y * v[j].y +
                        v[i].z * v[j].z + v[i].w * v[j].w;
                }
            }
        }
    }

    // warp-level reduce each dot, lane 0 atomics into g_dots
    #pragma unroll
    for (int i = 0; i < 10; i++) {
        if (i < nr) {
            #pragma unroll
            for (int j = 0; j <= i; j++) {
                float v = acc[i * (i + 1) / 2 + j];
                #pragma unroll
                for (int o = 16; o > 0; o >>= 1)
                    v += __shfl_down_sync(0xffffffffu, v, o);
                if ((threadIdx.x & 31) == 0)
                    atomicAdd(&g_dots[b * 100 + i * 10 + j], v);
            }
        }
    }
}

// ---------------------------------------------------------------------------
// Kernel 3: fused softmax-weight + weighted row sum.
// grid: (D4/256, TT) = (66, 10), block 256.
// ---------------------------------------------------------------------------
__global__ __launch_bounds__(256) void out_kernel(const float* __restrict__ ff,
                                                  float* __restrict__ out) {
    int b = blockIdx.y;
    int tid = threadIdx.x;
    __shared__ float contrib[10][10];   // [t][slot] = softmax(S[t])[slot]
    __shared__ float w[10];             // row-space weights

    if (tid < 10) {
        int t = tid;
        float S[10];
        #pragma unroll
        for (int s = 0; s < 10; s++) {
            bool vt = (t >= 9 - b), vs = (s >= 9 - b);
            float v = 0.f;
            if (vt && vs) {
                int rt = (t == 9) ? b : (8 - t);
                int rs = (s == 9) ? b : (8 - s);
                int lo = min(rt, rs), hi = max(rt, rs);
                v = g_dots[b * 100 + hi * 10 + lo];
            }
            S[s] = v;
        }
        float m = S[0];
        #pragma unroll
        for (int s = 1; s < 10; s++) m = fmaxf(m, S[s]);
        float e[10], z = 0.f;
        #pragma unroll
        for (int s = 0; s < 10; s++) { e[s] = expf(S[s] - m); z += e[s]; }
        float inv = 1.f / z;
        #pragma unroll
        for (int s = 0; s < 10; s++) contrib[t][s] = e[s] * inv;
    }
    __syncthreads();
    if (tid < 10) {
        int r = tid;
        float acc = 0.f;
        if (r <= b) {
            int slot = (r == b) ? 9 : (8 - r);
            #pragma unroll
            for (int t = 0; t < 10; t++) acc += contrib[t][slot];
        }
        w[r] = acc * (1.f / (float)TT);
    }
    __syncthreads();

    int d = blockIdx.x * 256 + tid;     // float4 index
    float4 a = ((const float4*)ff)[b * D4 + d];
    float wb = w[b];
    float4 acc = make_float4(wb * a.x, wb * a.y, wb * a.z, wb * a.w);
    for (int r = 0; r < b; r++) {
        float4 v = ((const float4*)g_warp)[(tri(b) + r) * D4 + d];
        float wr = w[r];
        acc.x += wr * v.x;
        acc.y += wr * v.y;
        acc.z += wr * v.z;
        acc.w += wr * v.w;
    }
    ((float4*)out)[b * D4 + d] = acc;
}

// ---------------------------------------------------------------------------
extern "C" void kernel_launch(void* const* d_in, const int* in_sizes, int n_in,
                              void* d_out, int out_size) {
    const float* ff = (const float*)d_in[0];   // fuse_feature (T,L,C) = (T,CH,H,W)
    const float* dp = (const float*)d_in[1];   // delta_ego_pos (T,3)
    float* out = (float*)d_out;

    warp_kernel<<<dim3(HW / 128, NPAIR), 128>>>(ff, dp);
    score_kernel<<<dim3(33, TT), 128>>>(ff);
    out_kernel<<<dim3(D4 / 256, TT), 256>>>(ff, out);
}